// round 7
// baseline (speedup 1.0000x reference)
#include <cuda_runtime.h>
#include <stdint.h>

#define NN      5000000
#define NGRAPHS 100000
#define NPG     50

#define SHIFT   15
#define RANGE   32768            // nodes per bucket (128KB fp32 smem)
#define NB      153              // ceil(NN / RANGE)
#define CAP     560000           // per-bucket edge capacity (mean 524288, huge slack)
#define SPLIT   8                // sub-CTAs per bucket in hist/agg passes

#define BT      512              // bin threads
#define TILE    4096             // edges per bin tile (8 per thread)

// ---- scratch (allocation-free: __device__ globals, zero-init .bss) ----
__device__ int   g_cnt[NB];
__device__ int   g_brow[NB * CAP];
__device__ int   g_bcol[NB * CAP];
__device__ int   g_degi[NN];
__device__ float g_dis[NN];
__device__ float g_s[NN];
__device__ float g_agg[NN];

// Reset per-call state (graph replays re-run everything).
__global__ void k_init(int n) {
    int i = blockIdx.x * blockDim.x + threadIdx.x;
    if (i < n) { g_degi[i] = 0; g_agg[i] = 0.0f; }
    if (i < NB) g_cnt[i] = 0;
}

// Multisplit: partition edges by col>>SHIFT into NB buckets, smem-staged so
// each bucket chunk is written coalesced.
__global__ void __launch_bounds__(BT) k_bin(const int* __restrict__ row,
                                            const int* __restrict__ col,
                                            int E, int ntiles) {
    __shared__ int cnt[256];
    __shared__ int offs[256];
    __shared__ int gbase[NB];
    __shared__ int srow[TILE];
    __shared__ int scol[TILE];

    const int t = threadIdx.x;
    const int warp = t >> 5, lane = t & 31;

    for (int tile = blockIdx.x; tile < ntiles; tile += gridDim.x) {
        int base = tile * TILE;
        int r[8], c[8], sl[8];

        if (t < 256) cnt[t] = 0;
        __syncthreads();

        #pragma unroll
        for (int k = 0; k < 8; k++) {
            int e = base + k * BT + t;
            if (e < E) {
                r[k] = row[e];
                c[k] = col[e];
                sl[k] = atomicAdd(&cnt[c[k] >> SHIFT], 1);
            } else {
                r[k] = -1;
            }
        }
        __syncthreads();

        // reserve global ranges
        if (t < NB) gbase[t] = atomicAdd(&g_cnt[t], cnt[t]);

        // inclusive scan of cnt[256] into offs (Hillis-Steele)
        if (t < 256) offs[t] = cnt[t];
        __syncthreads();
        for (int d = 1; d < 256; d <<= 1) {
            int add = 0;
            if (t < 256 && t >= d) add = offs[t - d];
            __syncthreads();
            if (t < 256 && t >= d) offs[t] += add;
            __syncthreads();
        }

        // stage into bucket-sorted smem (exclusive offset = offs[b]-cnt[b])
        #pragma unroll
        for (int k = 0; k < 8; k++) {
            if (r[k] >= 0) {
                int b = c[k] >> SHIFT;
                int p = offs[b] - cnt[b] + sl[k];
                srow[p] = r[k];
                scol[p] = c[k];
            }
        }
        __syncthreads();

        // coalesced copy-out, one warp per bucket round-robin
        for (int b = warp; b < NB; b += (BT / 32)) {
            int n   = cnt[b];
            int src = offs[b] - n;
            int dst = b * CAP + gbase[b];
            for (int i = lane; i < n; i += 32) {
                g_brow[dst + i] = srow[src + i];
                g_bcol[dst + i] = scol[src + i];
            }
        }
        __syncthreads();   // protect smem before next tile
    }
}

// Degree: per (bucket, part) CTA, smem int histogram + coalesced RED of partials.
__global__ void __launch_bounds__(1024) k_degree() {
    extern __shared__ int sh[];
    const int b = blockIdx.x / SPLIT;
    const int part = blockIdx.x % SPLIT;
    const int t = threadIdx.x;

    for (int j = t; j < RANGE; j += 1024) sh[j] = 0;
    __syncthreads();

    const int n  = g_cnt[b];
    const int s0 = (int)((long long)n * part / SPLIT);
    const int s1 = (int)((long long)n * (part + 1) / SPLIT);
    const int* __restrict__ bc = g_bcol + b * CAP;

    for (int i = s0 + t; i < s1; i += 1024)
        atomicAdd(&sh[__ldg(&bc[i]) & (RANGE - 1)], 1);
    __syncthreads();

    const int nodebase = b << SHIFT;
    for (int j = t; j < RANGE; j += 1024) {
        int node = nodebase + j;
        int v = sh[j];
        if (node < NN && v) atomicAdd(&g_degi[node], v);
    }
}

// Per-node: dis = rsqrt(deg+1 self loop), s = x*w*dis.
__global__ void k_node(const float* __restrict__ x,
                       const float* __restrict__ conv_w, int n) {
    int i = blockIdx.x * blockDim.x + threadIdx.x;
    if (i < n) {
        float w   = __ldg(conv_w);
        float dis = rsqrtf((float)(g_degi[i] + 1));
        g_dis[i]  = dis;
        g_s[i]    = x[i] * w * dis;
    }
}

// Scatter: smem float accumulation per bucket + coalesced RED of partials.
__global__ void __launch_bounds__(1024) k_scatter() {
    extern __shared__ float shf[];
    const int b = blockIdx.x / SPLIT;
    const int part = blockIdx.x % SPLIT;
    const int t = threadIdx.x;

    for (int j = t; j < RANGE; j += 1024) shf[j] = 0.0f;
    __syncthreads();

    const int n  = g_cnt[b];
    const int s0 = (int)((long long)n * part / SPLIT);
    const int s1 = (int)((long long)n * (part + 1) / SPLIT);
    const int* __restrict__ br = g_brow + b * CAP;
    const int* __restrict__ bc = g_bcol + b * CAP;

    int i = s0 + t;
    // 4-way batching for MLP on the random g_s gathers
    for (; i + 3 * 1024 < s1; i += 4 * 1024) {
        int r0 = __ldg(&br[i]),        r1 = __ldg(&br[i + 1024]);
        int r2 = __ldg(&br[i + 2048]), r3 = __ldg(&br[i + 3072]);
        int c0 = __ldg(&bc[i]),        c1 = __ldg(&bc[i + 1024]);
        int c2 = __ldg(&bc[i + 2048]), c3 = __ldg(&bc[i + 3072]);
        float v0 = __ldg(&g_s[r0]), v1 = __ldg(&g_s[r1]);
        float v2 = __ldg(&g_s[r2]), v3 = __ldg(&g_s[r3]);
        atomicAdd(&shf[c0 & (RANGE - 1)], v0);
        atomicAdd(&shf[c1 & (RANGE - 1)], v1);
        atomicAdd(&shf[c2 & (RANGE - 1)], v2);
        atomicAdd(&shf[c3 & (RANGE - 1)], v3);
    }
    for (; i < s1; i += 1024) {
        int r = __ldg(&br[i]);
        int c = __ldg(&bc[i]);
        atomicAdd(&shf[c & (RANGE - 1)], __ldg(&g_s[r]));
    }
    __syncthreads();

    const int nodebase = b << SHIFT;
    for (int j = t; j < RANGE; j += 1024) {
        int node = nodebase + j;
        float v = shf[j];
        if (node < NN && v != 0.0f) atomicAdd(&g_agg[node], v);
    }
}

// Head: h = (agg + s)*dis + conv_b, then per-graph 50-dot with fc_w.
__global__ void k_head(const float* __restrict__ conv_b,
                       const float* __restrict__ fc_w,
                       const float* __restrict__ fc_b,
                       float* __restrict__ out, int ngraphs) {
    __shared__ float w0[NPG];
    __shared__ float w1[NPG];
    if (threadIdx.x < NPG) {
        w0[threadIdx.x] = fc_w[threadIdx.x];
        w1[threadIdx.x] = fc_w[NPG + threadIdx.x];
    }
    __syncthreads();
    int g = blockIdx.x * blockDim.x + threadIdx.x;
    if (g < ngraphs) {
        float bb = __ldg(conv_b);
        float a0 = __ldg(&fc_b[0]);
        float a1 = __ldg(&fc_b[1]);
        int base = g * NPG;
        #pragma unroll
        for (int j = 0; j < NPG; j++) {
            float h = fmaf(g_agg[base + j] + g_s[base + j], g_dis[base + j], bb);
            a0 = fmaf(h, w0[j], a0);
            a1 = fmaf(h, w1[j], a1);
        }
        out[2 * g]     = a0;
        out[2 * g + 1] = a1;
    }
}

extern "C" void kernel_launch(void* const* d_in, const int* in_sizes, int n_in,
                              void* d_out, int out_size) {
    const float* x      = (const float*)d_in[0];
    const int*   eidx   = (const int*)d_in[1];     // int32 (JAX x64 disabled)
    const float* conv_w = (const float*)d_in[2];
    const float* conv_b = (const float*)d_in[3];
    const float* fc_w   = (const float*)d_in[4];
    const float* fc_b   = (const float*)d_in[5];
    float*       out    = (float*)d_out;

    const int n = in_sizes[0];          // 5,000,000
    const int E = in_sizes[1] / 2;      // 80,000,000
    const int* row = eidx;
    const int* col = eidx + E;
    const int ntiles = (E + TILE - 1) / TILE;

    static bool attr_done = false;
    if (!attr_done) {
        cudaFuncSetAttribute(k_degree,  cudaFuncAttributeMaxDynamicSharedMemorySize, RANGE * 4);
        cudaFuncSetAttribute(k_scatter, cudaFuncAttributeMaxDynamicSharedMemorySize, RANGE * 4);
        attr_done = true;
    }

    const int T = 256;
    k_init   <<<(n + T - 1) / T, T>>>(n);
    k_bin    <<<444, BT>>>(row, col, E, ntiles);
    k_degree <<<NB * SPLIT, 1024, RANGE * 4>>>();
    k_node   <<<(n + T - 1) / T, T>>>(x, conv_w, n);
    k_scatter<<<NB * SPLIT, 1024, RANGE * 4>>>();
    k_head   <<<(NGRAPHS + T - 1) / T, T>>>(conv_b, fc_w, fc_b, out, NGRAPHS);
}